// round 2
// baseline (speedup 1.0000x reference)
#include <cuda_runtime.h>
#include <cstdint>

// ---------------------------------------------------------------------------
// Row_Averaging: x [B=65536, C=1, H=28, W=28] fp32.
// For sample b, any row h with pos[h] < t[b] is replaced by mean(x[b,0,h,:]).
// pos = inverse permutation of rows_t (the interleaved fwd/bwd schedule).
//
// One thread per (b,h) row: 7 x LDG.128 + reduce + 7 x STG.128. Pure HBM
// streaming (411 MB total traffic). Roofline ~60-80 us on B200.
// ---------------------------------------------------------------------------

#define HH 28

__device__ int g_pos[HH];     // pos[row] = schedule position
__device__ int g_t_is64;      // 1 if t is stored as int64

__global__ void build_pos_kernel(const void* rows_raw, const void* t_raw) {
    int h = threadIdx.x;
    if (h == 0) {
        // Detect t dtype by value: int64 layout -> first 8 bytes is small
        // (1..27). int32 layout -> the i64 reinterpretation of two int32
        // values (each >=1) is >= 2^32.
        long long t0 = *(const long long*)t_raw;
        g_t_is64 = (t0 >= 0 && t0 < HH) ? 1 : 0;
    }
    if (h < HH) {
        long long r0 = *(const long long*)rows_raw;
        bool rows64 = (r0 >= 0 && r0 < HH);
        int row;
        if (rows64) row = (int)((const long long*)rows_raw)[h];
        else        row = ((const int*)rows_raw)[h];
        g_pos[row] = h;
    }
}

__global__ __launch_bounds__(256)
void row_avg_kernel(const float4* __restrict__ x4,
                    const void*   __restrict__ t_raw,
                    float4*       __restrict__ out4,
                    int nrows) {
    int row = blockIdx.x * blockDim.x + threadIdx.x;
    if (row >= nrows) return;

    unsigned b = (unsigned)row / HH;
    unsigned h = (unsigned)row - b * HH;

    const float4* p = x4 + (size_t)row * 7;
    float4 v0 = p[0], v1 = p[1], v2 = p[2], v3 = p[3];
    float4 v4 = p[4], v5 = p[5], v6 = p[6];

    float s = ((v0.x + v0.y) + (v0.z + v0.w))
            + ((v1.x + v1.y) + (v1.z + v1.w))
            + ((v2.x + v2.y) + (v2.z + v2.w))
            + ((v3.x + v3.y) + (v3.z + v3.w))
            + ((v4.x + v4.y) + (v4.z + v4.w))
            + ((v5.x + v5.y) + (v5.z + v5.w))
            + ((v6.x + v6.y) + (v6.z + v6.w));
    float mean = s * (1.0f / 28.0f);

    int tb;
    if (g_t_is64) {
        tb = (int)__ldg((const long long*)t_raw + b);
    } else {
        tb = __ldg((const int*)t_raw + b);
    }

    bool replace = (g_pos[h] < tb);

    float4* o = out4 + (size_t)row * 7;
    if (replace) {
        float4 m = make_float4(mean, mean, mean, mean);
        o[0] = m; o[1] = m; o[2] = m; o[3] = m;
        o[4] = m; o[5] = m; o[6] = m;
    } else {
        o[0] = v0; o[1] = v1; o[2] = v2; o[3] = v3;
        o[4] = v4; o[5] = v5; o[6] = v6;
    }
}

extern "C" void kernel_launch(void* const* d_in, const int* in_sizes, int n_in,
                              void* d_out, int out_size) {
    const void* x      = d_in[0];   // float32 [B,1,28,28]
    const void* t      = d_in[1];   // int   [B]
    const void* rows_t = d_in[2];   // int   [28]

    int total = out_size;           // B*1*28*28 elements
    int nrows = total / HH;         // B*28

    build_pos_kernel<<<1, HH>>>(rows_t, t);

    int threads = 256;
    int blocks = (nrows + threads - 1) / threads;
    row_avg_kernel<<<blocks, threads>>>((const float4*)x, t,
                                        (float4*)d_out, nrows);
}

// round 4
// speedup vs baseline: 1.2702x; 1.2702x over previous
#include <cuda_runtime.h>
#include <cstdint>

// ---------------------------------------------------------------------------
// Row_Averaging: x [B=65536, C=1, H=28, W=28] fp32.
// For sample b, any row h with pos[h] < t[b] is replaced by mean(x[b,0,h,:]).
//
// Fully-coalesced tiled version. Block of 256 threads stages 256 rows
// (1792 float4) with contiguous lane->float4 mapping; row sums assembled in
// shared memory. Removes the ~7x L1/L2 wavefront amplification of the
// one-thread-per-row layout (R2 ncu: L2 82% busy vs DRAM 54%).
// ---------------------------------------------------------------------------

#define HH 28
#define RPB 256                 // rows per block
#define F4PB (RPB * 7)          // float4 per block = 1792

__device__ int g_pos[HH];       // pos[row] = schedule position
__device__ int g_t_is64;        // 1 if t is stored as int64

__global__ void build_pos_kernel(const void* rows_raw, const void* t_raw) {
    int h = threadIdx.x;
    if (h == 0) {
        // Detect t dtype by value: int64 layout -> first 8 bytes small (1..27);
        // int32 layout -> i64 reinterpretation of two int32 (each >=1) >= 2^32.
        long long t0 = *(const long long*)t_raw;
        g_t_is64 = (t0 >= 0 && t0 < HH) ? 1 : 0;
    }
    if (h < HH) {
        long long r0 = *(const long long*)rows_raw;
        bool rows64 = (r0 >= 0 && r0 < HH);
        int row;
        if (rows64) row = (int)((const long long*)rows_raw)[h];
        else        row = ((const int*)rows_raw)[h];
        g_pos[row] = h;
    }
}

__global__ __launch_bounds__(256)
void row_avg_kernel(const float4* __restrict__ x4,
                    const void*   __restrict__ t_raw,
                    float4*       __restrict__ out4,
                    int nrows) {
    __shared__ float part[F4PB];        // per-float4 partial sums
    __shared__ float rmean[RPB];
    __shared__ int   rflag[RPB];

    const int tid = threadIdx.x;
    const size_t base = (size_t)blockIdx.x * F4PB;
    const size_t total_f4 = (size_t)nrows * 7;

    float4 v[7];

    // Phase 1: coalesced loads + per-float4 partial sums into smem.
    #pragma unroll
    for (int k = 0; k < 7; k++) {
        size_t idx = base + (size_t)k * 256 + tid;
        float4 w = (idx < total_f4) ? x4[idx]
                                    : make_float4(0.f, 0.f, 0.f, 0.f);
        v[k] = w;
        part[k * 256 + tid] = (w.x + w.y) + (w.z + w.w);
    }
    __syncthreads();

    // Phase 2: one thread per row -> row mean + replace flag.
    {
        const int r = tid;
        const int grow = blockIdx.x * RPB + r;    // global row id
        float s = ((part[7*r + 0] + part[7*r + 1])
                 + (part[7*r + 2] + part[7*r + 3]))
                 + ((part[7*r + 4] + part[7*r + 5])
                 +  part[7*r + 6]);
        rmean[r] = s * (1.0f / 28.0f);

        int flag = 0;
        if (grow < nrows) {
            unsigned b = (unsigned)grow / HH;
            unsigned h = (unsigned)grow - b * HH;
            int tb;
            if (g_t_is64) tb = (int)__ldg((const long long*)t_raw + b);
            else          tb = __ldg((const int*)t_raw + b);
            flag = (g_pos[h] < tb);
        }
        rflag[r] = flag;
    }
    __syncthreads();

    // Phase 3: coalesced streaming stores, mean vs original per float4.
    #pragma unroll
    for (int k = 0; k < 7; k++) {
        const int j = k * 256 + tid;        // tile-local float4 index
        const size_t idx = base + j;
        if (idx >= total_f4) continue;
        const int r = j / 7;                // tile-local row
        const float m = rmean[r];
        const float4 o = rflag[r] ? make_float4(m, m, m, m) : v[k];
        __stcs(&out4[idx], o);
    }
}

extern "C" void kernel_launch(void* const* d_in, const int* in_sizes, int n_in,
                              void* d_out, int out_size) {
    const void* x      = d_in[0];   // float32 [B,1,28,28]
    const void* t      = d_in[1];   // int   [B]
    const void* rows_t = d_in[2];   // int   [28]

    int total = out_size;           // B*1*28*28 elements
    int nrows = total / HH;         // B*28

    build_pos_kernel<<<1, HH>>>(rows_t, t);

    int blocks = (nrows + RPB - 1) / RPB;
    row_avg_kernel<<<blocks, 256>>>((const float4*)x, t,
                                    (float4*)d_out, nrows);
}